// round 13
// baseline (speedup 1.0000x reference)
#include <cuda_runtime.h>
#include <cuda_fp16.h>
#include <math.h>
#include <stdint.h>

#define BB 32
#define PP 2048
#define KK 16
#define NH 128
#define NSEG 4
#define SEGC (PP / NSEG)       // 512 candidates per segment
#define KNN_CAP 16

typedef unsigned long long u64;

// Scratch (no allocations allowed).
__device__ int   g_nbr[BB * PP * KK];
__device__ u64   g_knnp[NSEG][BB * PP][KK];
__device__ float g_t [BB * PP * NH];
__device__ float g_h2[BB * PP * NH];
__device__ float g_part[BB][8][NH];
// Weight fragments (fp16) in mma B register order:
// [mat][(nt*8+kc)*32+lane] -> uint2{b0,b1};  mat: 0=W1b, 1=W2b, 2=W2a[0:128]
__device__ uint2 g_wfh[3][16 * 8 * 32];

// ---- helpers ---------------------------------------------------------------
__device__ __forceinline__ uint32_t smem_u32(const void* p) {
    return (uint32_t)__cvta_generic_to_shared(p);
}
__device__ __forceinline__ uint32_t pack_h2(float a, float b) {
    const __half2 h = __floats2half2_rn(a, b);
    return *(const uint32_t*)&h;
}
__device__ __forceinline__ void ldsm_x4(uint32_t* r, uint32_t addr) {
    asm volatile("ldmatrix.sync.aligned.m8n8.x4.shared.b16 {%0,%1,%2,%3}, [%4];"
                 : "=r"(r[0]), "=r"(r[1]), "=r"(r[2]), "=r"(r[3]) : "r"(addr));
}
__device__ __forceinline__ void mma_f16(float* d, const uint32_t* a, uint2 b) {
    asm volatile(
        "mma.sync.aligned.m16n8k16.row.col.f32.f16.f16.f32 "
        "{%0,%1,%2,%3}, {%4,%5,%6,%7}, {%8,%9}, {%0,%1,%2,%3};"
        : "+f"(d[0]), "+f"(d[1]), "+f"(d[2]), "+f"(d[3])
        : "r"(a[0]), "r"(a[1]), "r"(a[2]), "r"(a[3]), "r"(b.x), "r"(b.y));
}
// order-preserving float->u32 (handles negative zeros / tiny negatives)
__device__ __forceinline__ u64 okey(float d, int idx) {
    uint32_t u = __float_as_uint(d);
    u = (u & 0x80000000u) ? ~u : (u | 0x80000000u);
    return ((u64)u << 32) | (uint32_t)idx;
}

// ---------------------------------------------------------------------------
// KNN segment pass: exact top-16 of each query over its 512-candidate segment.
// grid (PP/128, NSEG, BB). Deferred-batched insertion (validated in R11).
// ---------------------------------------------------------------------------
__global__ void knn_seg_kernel(const float* __restrict__ pos) {
    __shared__ float4 tile[128];
    __shared__ u64 buf[128][KNN_CAP];

    const int tid = threadIdx.x;
    const int seg = blockIdx.y;
    const int b   = blockIdx.z;
    const int q   = blockIdx.x * blockDim.x + tid;
    const float* pb = pos + (size_t)b * PP * 3;
    const int c0  = seg * SEGC;

    const float qx = pb[q * 3 + 0];
    const float qy = pb[q * 3 + 1];
    const float qz = pb[q * 3 + 2];
    const float qsq = qx * qx + qy * qy + qz * qz;

    float kd[KK];
    int   ki[KK];
#pragma unroll
    for (int s = 0; s < KK; ++s) { kd[s] = 3.4e38f; ki[s] = -1; }

    float T = 3.4e38f;
    int cnt = 0;

#define CHAIN_INSERT(dd, jj2)                                                  \
    do {                                                                       \
        kd[KK - 1] = (dd); ki[KK - 1] = (jj2);                                 \
        _Pragma("unroll")                                                      \
        for (int s = KK - 1; s > 0; --s) {                                     \
            if (kd[s] < kd[s - 1]) {                                           \
                const float td = kd[s]; kd[s] = kd[s - 1]; kd[s - 1] = td;     \
                const int   ti = ki[s]; ki[s] = ki[s - 1]; ki[s - 1] = ti;     \
            }                                                                  \
        }                                                                      \
    } while (0)

#define FLUSH_BUF()                                                            \
    do {                                                                       \
        for (int i = 0; i < cnt; ++i) {                                        \
            const u64 kk = buf[tid][i];                                        \
            const float dd = __uint_as_float((uint32_t)(kk >> 32));            \
            const int jj2 = (int)(kk & 0xffffffffu);                           \
            if (dd < kd[KK - 1]) CHAIN_INSERT(dd, jj2);                        \
        }                                                                      \
        cnt = 0; T = kd[KK - 1];                                               \
    } while (0)

    for (int t0 = 0; t0 < SEGC; t0 += 128) {
        const int j = c0 + t0 + tid;
        const float x = pb[j * 3 + 0];
        const float y = pb[j * 3 + 1];
        const float z = pb[j * 3 + 2];
        tile[tid] = make_float4(x, y, z, x * x + y * y + z * z);
        __syncthreads();

        if (t0 == 0) {
#pragma unroll 4
            for (int jj = 0; jj < 128; ++jj) {
                const float4 c = tile[jj];
                const float dot = qx * c.x + qy * c.y + qz * c.z;
                const float d2  = (qsq + c.w) - 2.0f * dot;
                if (d2 < kd[KK - 1]) CHAIN_INSERT(d2, c0 + jj);
            }
            T = kd[KK - 1];
        } else {
#pragma unroll 4
            for (int jj = 0; jj < 128; ++jj) {
                const float4 c = tile[jj];
                const float dot = qx * c.x + qy * c.y + qz * c.z;
                const float d2  = (qsq + c.w) - 2.0f * dot;
                if (d2 < T) {
                    if (cnt == KNN_CAP) FLUSH_BUF();
                    buf[tid][cnt++] = ((u64)__float_as_uint(d2) << 32) |
                                      (uint32_t)(c0 + t0 + jj);
                }
            }
            FLUSH_BUF();
        }
        __syncthreads();
    }

    u64* dst = g_knnp[seg][b * PP + q];
#pragma unroll
    for (int s = 0; s < KK; ++s) dst[s] = okey(kd[s], ki[s]);
#undef CHAIN_INSERT
#undef FLUSH_BUF
}

// ---------------------------------------------------------------------------
// KNN merge: 4-way merge of sorted segment lists (u64 keys -> exact order,
// lower-index tie-break). Thread = query.
// ---------------------------------------------------------------------------
__global__ void knn_merge_kernel() {
    const int gq = blockIdx.x * blockDim.x + threadIdx.x;   // b*PP+q

    int pi[NSEG];
    u64 cur[NSEG];
#pragma unroll
    for (int s = 0; s < NSEG; ++s) { pi[s] = 0; cur[s] = g_knnp[s][gq][0]; }

    int* dst = g_nbr + (size_t)gq * KK;
#pragma unroll
    for (int o = 0; o < KK; ++o) {
        int best = 0;
        u64 bk = cur[0];
#pragma unroll
        for (int s = 1; s < NSEG; ++s)
            if (cur[s] < bk) { bk = cur[s]; best = s; }
        dst[o] = (int)(bk & 0xffffffffu);
        const int np = ++pi[best];
        cur[best] = (np < KK) ? g_knnp[best][gq][np] : ~0ull;
    }
}

// ---------------------------------------------------------------------------
// Weight prep (one matrix per launch): fp16 fragments (col-major [n,k]).
// ---------------------------------------------------------------------------
__global__ void wprep_kernel(const float* __restrict__ W, int L) {
    const int nt = blockIdx.x, kc = blockIdx.y;
    const int l  = threadIdx.x;
    const int n  = nt * 8 + (l >> 2);
    const int k0 = kc * 16 + (l & 3) * 2;

    float v[4];
    v[0] = W[(k0 + 0) * NH + n];
    v[1] = W[(k0 + 1) * NH + n];
    v[2] = W[(k0 + 8) * NH + n];
    v[3] = W[(k0 + 9) * NH + n];
    const int idx = (nt * 8 + kc) * 32 + l;
    g_wfh[L][idx] = make_uint2(pack_h2(v[0], v[1]), pack_h2(v[2], v[3]));
}

// ---------------------------------------------------------------------------
// Edge-conv layer via mma.sync fp16 (fp32 accumulate). CTA = 8 pts = 128 edges.
// GEMM: 4 n-tiles fused per A-fragment. MODE1 additionally computes
// t = h1 @ W2a + b2a in-kernel (mini-MMA) and writes only g_t.
// ---------------------------------------------------------------------------
template <int MODE>
__global__ __launch_bounds__(128, 5) void layer_mma(
    const float* __restrict__ pos,
    const float* __restrict__ Wsmall,   // MODE1: W1a[6,128]; MODE2: W2a rows 128..130
    const float* __restrict__ bh,       // MODE1: b1a
    const float* __restrict__ bo,       // MODE1: b1b; MODE2: b2b
    const float* __restrict__ b2a)      // MODE1 only
{
    extern __shared__ char dsm[];
    __shared__ float sM[8][KK][6];
    __shared__ int   sJ[8][KK];

    const int tid = threadIdx.x;
    const int wid = tid >> 5, lid = tid & 31;
    const int p0  = blockIdx.x * 8;
    const int L   = MODE - 1;

    char* actH = (char*)(((uintptr_t)dsm + 1023) & ~(uintptr_t)1023);
    char* h1t  = actH + 32768;          // MODE1: 4KB fp16 h1 tile (16 rows x 128)

    // MODE1: zero h1 tile rows 8-15 (bytes [2048,4096))
    if (MODE == 1)
        *(uint4*)(h1t + 2048 + tid * 16) = make_uint4(0u, 0u, 0u, 0u);

    // ---- neighbor / message prep: thread -> (pt = tid>>4, k = tid&15) ------
    {
        const int pt = tid >> 4, k = tid & 15;
        const int p  = p0 + pt;
        const int b  = p / PP;
        const int jg = b * PP + g_nbr[p * KK + k];
        sJ[pt][k] = jg;
        const float pjx = pos[jg * 3 + 0], pjy = pos[jg * 3 + 1], pjz = pos[jg * 3 + 2];
        const float pix = pos[p * 3 + 0],  piy = pos[p * 3 + 1],  piz = pos[p * 3 + 2];
        if (MODE == 1) {
            sM[pt][k][0] = pjx; sM[pt][k][1] = pjy; sM[pt][k][2] = pjz;
            sM[pt][k][3] = pjx - pix; sM[pt][k][4] = pjy - piy; sM[pt][k][5] = pjz - piz;
        } else {
            sM[pt][k][0] = pjx - pix; sM[pt][k][1] = pjy - piy; sM[pt][k][2] = pjz - piz;
        }
    }
    __syncthreads();

    // ---- Stage A: warp w builds edges 32w..32w+31; lane owns dims 4l..4l+3 -
    {
        const int d0 = lid * 4;
        float4 wsm4[6];
        const int NSM = (MODE == 1) ? 6 : 3;
#pragma unroll
        for (int u = 0; u < 6; ++u)
            wsm4[u] = (u < NSM) ? *(const float4*)&Wsmall[u * NH + d0]
                                : make_float4(0.f, 0.f, 0.f, 0.f);
        float4 bh4 = make_float4(0.f, 0.f, 0.f, 0.f);
        if (MODE == 1) bh4 = *(const float4*)&bh[d0];

        const uint32_t lane_off = (((uint32_t)(lid >> 1)) << 4) + ((lid & 1) << 3);

#pragma unroll 4
        for (int i = 0; i < 32; ++i) {
            const int e  = wid * 32 + i;
            const int pt = e >> 4, k = e & 15;
            float h0, h1, h2, h3;
            if (MODE == 1) {
                h0 = bh4.x; h1 = bh4.y; h2 = bh4.z; h3 = bh4.w;
#pragma unroll
                for (int u = 0; u < 6; ++u) {
                    const float mu = sM[pt][k][u];
                    h0 = fmaf(mu, wsm4[u].x, h0);
                    h1 = fmaf(mu, wsm4[u].y, h1);
                    h2 = fmaf(mu, wsm4[u].z, h2);
                    h3 = fmaf(mu, wsm4[u].w, h3);
                }
            } else {
                const float4 t4 = *(const float4*)&g_t[(size_t)sJ[pt][k] * NH + d0];
                h0 = t4.x; h1 = t4.y; h2 = t4.z; h3 = t4.w;
#pragma unroll
                for (int u = 0; u < 3; ++u) {
                    const float mu = sM[pt][k][u];
                    h0 = fmaf(mu, wsm4[u].x, h0);
                    h1 = fmaf(mu, wsm4[u].y, h1);
                    h2 = fmaf(mu, wsm4[u].z, h2);
                    h3 = fmaf(mu, wsm4[u].w, h3);
                }
            }
            h0 = fmaxf(h0, 0.f); h1 = fmaxf(h1, 0.f);
            h2 = fmaxf(h2, 0.f); h3 = fmaxf(h3, 0.f);

            // row e layout: byte(d) = e*256 + (((d>>3)^(e&7))<<4) + ((d*2)&15)
            const uint32_t off = (uint32_t)e * 256 +
                                 (lane_off ^ (((uint32_t)(e & 7)) << 4));
            *(uint2*)(actH + off) = make_uint2(pack_h2(h0, h1), pack_h2(h2, h3));
        }
    }
    __syncthreads();

    // ---- GEMM: mt-half outer, 4 n-tiles fused per A-fragment ---------------
    const uint32_t aHs = smem_u32(actH);
    const int rowl  = (lid & 15);
    const int kxofs = (lid >> 4) & 1;

#pragma unroll
    for (int mh = 0; mh < 2; ++mh) {
        float acc[4][4][4];
#pragma unroll
        for (int mt = 0; mt < 4; ++mt)
#pragma unroll
            for (int j = 0; j < 4; ++j)
#pragma unroll
                for (int c = 0; c < 4; ++c) acc[mt][j][c] = 0.f;

#pragma unroll
        for (int kc = 0; kc < 8; ++kc) {
            uint2 bf[4];
#pragma unroll
            for (int j = 0; j < 4; ++j)
                bf[j] = g_wfh[L][((wid * 4 + j) * 8 + kc) * 32 + lid];
            const int kx = kc * 2 + kxofs;

#pragma unroll
            for (int mt = 0; mt < 4; ++mt) {
                const int r = (mh * 4 + mt) * 16 + rowl;
                const uint32_t off = ((uint32_t)r << 8) +
                                     ((uint32_t)(kx ^ (r & 7)) << 4);
                uint32_t ah[4];
                ldsm_x4(ah, aHs + off);
                mma_f16(acc[mt][0], ah, bf[0]);
                mma_f16(acc[mt][1], ah, bf[1]);
                mma_f16(acc[mt][2], ah, bf[2]);
                mma_f16(acc[mt][3], ah, bf[3]);
            }
        }

        // epilogue: max over 16 edge rows per point, bias, relu
#pragma unroll
        for (int mt = 0; mt < 4; ++mt) {
            const int prow = mh * 4 + mt;            // point index in CTA
#pragma unroll
            for (int j = 0; j < 4; ++j) {
                float c0 = fmaxf(acc[mt][j][0], acc[mt][j][2]);
                float c1 = fmaxf(acc[mt][j][1], acc[mt][j][3]);
#pragma unroll
                for (int s = 4; s <= 16; s <<= 1) {
                    c0 = fmaxf(c0, __shfl_xor_sync(0xffffffffu, c0, s));
                    c1 = fmaxf(c1, __shfl_xor_sync(0xffffffffu, c1, s));
                }
                if (lid < 4) {
                    const int nt = wid * 4 + j;
                    const int n0 = nt * 8 + 2 * lid;
                    const float2 bv = *(const float2*)&bo[n0];
                    const float o0 = fmaxf(c0 + bv.x, 0.f);
                    const float o1 = fmaxf(c1 + bv.y, 0.f);
                    if (MODE == 1) {
                        // h1 -> fp16 smem tile (row = prow, cols n0,n0+1)
                        const uint32_t hoff = (uint32_t)prow * 256 +
                            ((uint32_t)(nt ^ prow) << 4) + (uint32_t)(4 * lid);
                        *(uint32_t*)(h1t + hoff) = pack_h2(o0, o1);
                    } else {
                        *(float2*)&g_h2[(size_t)(p0 + prow) * NH + n0] =
                            make_float2(o0, o1);
                    }
                }
            }
        }
    }

    // ---- MODE1 mini-GEMM: t[8,128] = h1[8,128] @ W2a[0:128] + b2a ----------
    if (MODE == 1) {
        __syncthreads();
        const uint32_t h1s = smem_u32(h1t);
        float acc2[4][4];
#pragma unroll
        for (int j = 0; j < 4; ++j)
#pragma unroll
            for (int c = 0; c < 4; ++c) acc2[j][c] = 0.f;

#pragma unroll
        for (int kc = 0; kc < 8; ++kc) {
            const int kx = kc * 2 + kxofs;
            const uint32_t off = ((uint32_t)rowl << 8) +
                                 ((uint32_t)(kx ^ (rowl & 7)) << 4);
            uint32_t ah[4];
            ldsm_x4(ah, h1s + off);
#pragma unroll
            for (int j = 0; j < 4; ++j) {
                const uint2 bf = g_wfh[2][((wid * 4 + j) * 8 + kc) * 32 + lid];
                mma_f16(acc2[j], ah, bf);
            }
        }

        // store rows 0-7 (d0,d1 -> row = lid>>2, cols 2*(lid&3)+{0,1})
        const int row = lid >> 2;
#pragma unroll
        for (int j = 0; j < 4; ++j) {
            const int n0 = (wid * 4 + j) * 8 + 2 * (lid & 3);
            const float2 bv = *(const float2*)&b2a[n0];
            *(float2*)&g_t[(size_t)(p0 + row) * NH + n0] =
                make_float2(acc2[j][0] + bv.x, acc2[j][1] + bv.y);
        }
    }
}

// ---------------------------------------------------------------------------
// Pool stage 1: partial max over 256-point segments.
// ---------------------------------------------------------------------------
__global__ void pool1_kernel() {
    const int b = blockIdx.y, seg = blockIdx.x;
    const int tid = threadIdx.x;
    const float* hb = g_h2 + ((size_t)b * PP + seg * 256) * NH;

    float m0 = -3.4e38f, m1 = m0, m2 = m0, m3 = m0;
    for (int p = 0; p < 256; p += 4) {
        m0 = fmaxf(m0, hb[(size_t)(p + 0) * NH + tid]);
        m1 = fmaxf(m1, hb[(size_t)(p + 1) * NH + tid]);
        m2 = fmaxf(m2, hb[(size_t)(p + 2) * NH + tid]);
        m3 = fmaxf(m3, hb[(size_t)(p + 3) * NH + tid]);
    }
    g_part[b][seg][tid] = fmaxf(fmaxf(m0, m1), fmaxf(m2, m3));
}

// ---------------------------------------------------------------------------
// Pool stage 2: combine partials + classifier.
// ---------------------------------------------------------------------------
__global__ void pool2_kernel(const float* __restrict__ Wc,
                             const float* __restrict__ bc,
                             float* __restrict__ out) {
    const int b   = blockIdx.x;
    const int tid = threadIdx.x;

    float m = g_part[b][0][tid];
#pragma unroll
    for (int s = 1; s < 8; ++s) m = fmaxf(m, g_part[b][s][tid]);

    __shared__ float sg[NH];
    sg[tid] = m;
    __syncthreads();

    if (tid < 10) {
        float a = bc[tid];
#pragma unroll 8
        for (int d = 0; d < NH; ++d) a = fmaf(sg[d], Wc[d * 10 + tid], a);
        out[b * 10 + tid] = a;
    }
}

// ---------------------------------------------------------------------------
extern "C" void kernel_launch(void* const* d_in, const int* in_sizes, int n_in,
                              void* d_out, int out_size) {
    const float* pos = (const float*)d_in[0];
    const float* W1a = (const float*)d_in[2];
    const float* b1a = (const float*)d_in[3];
    const float* W1b = (const float*)d_in[4];
    const float* b1b = (const float*)d_in[5];
    const float* W2a = (const float*)d_in[6];
    const float* b2a = (const float*)d_in[7];
    const float* W2b = (const float*)d_in[8];
    const float* b2b = (const float*)d_in[9];
    const float* Wc  = (const float*)d_in[10];
    const float* bc  = (const float*)d_in[11];
    float* out = (float*)d_out;

    const int DSM1 = 32768 + 4096 + 1024;  // act tile + h1 tile + pad
    const int DSM2 = 32768 + 1024;         // act tile + pad
    cudaFuncSetAttribute(layer_mma<1>, cudaFuncAttributeMaxDynamicSharedMemorySize, DSM1);
    cudaFuncSetAttribute(layer_mma<2>, cudaFuncAttributeMaxDynamicSharedMemorySize, DSM2);

    wprep_kernel<<<dim3(16, 8), 32>>>(W1b, 0);
    wprep_kernel<<<dim3(16, 8), 32>>>(W2b, 1);
    wprep_kernel<<<dim3(16, 8), 32>>>(W2a, 2);
    knn_seg_kernel<<<dim3(PP / 128, NSEG, BB), 128>>>(pos);
    knn_merge_kernel<<<BB * PP / 128, 128>>>();
    layer_mma<1><<<BB * PP / 8, 128, DSM1>>>(pos, W1a, b1a, b1b, b2a);
    layer_mma<2><<<BB * PP / 8, 128, DSM2>>>(pos, W2a + 128 * NH, nullptr, b2b, nullptr);
    pool1_kernel<<<dim3(8, BB), 128>>>();
    pool2_kernel<<<BB, 128>>>(Wc, bc, out);
}

// round 14
// speedup vs baseline: 1.2754x; 1.2754x over previous
#include <cuda_runtime.h>
#include <cuda_fp16.h>
#include <math.h>
#include <stdint.h>

#define BB 32
#define PP 2048
#define KK 16
#define NH 128
#define KNN_CAP 24

typedef unsigned long long u64;

// Scratch (no allocations allowed).
__device__ int   g_nbr[BB * PP * KK];
__device__ float g_t [BB * PP * NH];
__device__ int   g_gmax[BB][NH];      // fp32 bits (values >= 0), atomicMax-able
// Weight fragments (fp16) in mma B register order:
// [mat][(nt*8+kc)*32+lane] -> uint2{b0,b1};  mat: 0=W1b, 1=W2b, 2=W2a[0:128]
__device__ uint2 g_wfh[3][16 * 8 * 32];

// ---- helpers ---------------------------------------------------------------
__device__ __forceinline__ uint32_t smem_u32(const void* p) {
    return (uint32_t)__cvta_generic_to_shared(p);
}
__device__ __forceinline__ uint32_t pack_h2(float a, float b) {
    const __half2 h = __floats2half2_rn(a, b);
    return *(const uint32_t*)&h;
}
__device__ __forceinline__ void ldsm_x4(uint32_t* r, uint32_t addr) {
    asm volatile("ldmatrix.sync.aligned.m8n8.x4.shared.b16 {%0,%1,%2,%3}, [%4];"
                 : "=r"(r[0]), "=r"(r[1]), "=r"(r[2]), "=r"(r[3]) : "r"(addr));
}
__device__ __forceinline__ void mma_f16(float* d, const uint32_t* a, uint2 b) {
    asm volatile(
        "mma.sync.aligned.m16n8k16.row.col.f32.f16.f16.f32 "
        "{%0,%1,%2,%3}, {%4,%5,%6,%7}, {%8,%9}, {%0,%1,%2,%3};"
        : "+f"(d[0]), "+f"(d[1]), "+f"(d[2]), "+f"(d[3])
        : "r"(a[0]), "r"(a[1]), "r"(a[2]), "r"(a[3]), "r"(b.x), "r"(b.y));
}

// ---------------------------------------------------------------------------
// KNN, single pass, deferred-batched insertion (validated R11). Tile 0 now
// bootstraps with the SAME buffer+flush mechanism in 16-candidate sub-batches
// (T finite after first 16 -> filters rest of tile). Accept set & order are
// identical to classic sorted-insert: threshold only over-accepts, the chain
// filters exactly, and flush preserves ascending candidate order.
// ---------------------------------------------------------------------------
__global__ void knn_kernel(const float* __restrict__ pos) {
    __shared__ float4 tile[128];
    __shared__ u64 buf[128][KNN_CAP];

    const int tid = threadIdx.x;
    const int b = blockIdx.y;
    const int q = blockIdx.x * blockDim.x + tid;
    const float* pb = pos + (size_t)b * PP * 3;

    const float qx = pb[q * 3 + 0];
    const float qy = pb[q * 3 + 1];
    const float qz = pb[q * 3 + 2];
    const float qsq = qx * qx + qy * qy + qz * qz;

    float kd[KK];
    int   ki[KK];
#pragma unroll
    for (int s = 0; s < KK; ++s) { kd[s] = 3.4e38f; ki[s] = -1; }

    float T = 3.4e38f;
    int cnt = 0;

#define CHAIN_INSERT(dd, jj2)                                                  \
    do {                                                                       \
        kd[KK - 1] = (dd); ki[KK - 1] = (jj2);                                 \
        _Pragma("unroll")                                                      \
        for (int s = KK - 1; s > 0; --s) {                                     \
            if (kd[s] < kd[s - 1]) {                                           \
                const float td = kd[s]; kd[s] = kd[s - 1]; kd[s - 1] = td;     \
                const int   ti = ki[s]; ki[s] = ki[s - 1]; ki[s - 1] = ti;     \
            }                                                                  \
        }                                                                      \
    } while (0)

#define FLUSH_BUF()                                                            \
    do {                                                                       \
        for (int i = 0; i < cnt; ++i) {                                        \
            const u64 kk = buf[tid][i];                                        \
            const float dd = __uint_as_float((uint32_t)(kk >> 32));            \
            const int jj2 = (int)(kk & 0xffffffffu);                           \
            if (dd < kd[KK - 1]) CHAIN_INSERT(dd, jj2);                        \
        }                                                                      \
        cnt = 0; T = kd[KK - 1];                                               \
    } while (0)

    for (int t0 = 0; t0 < PP; t0 += 128) {
        const int j = t0 + tid;
        const float x = pb[j * 3 + 0];
        const float y = pb[j * 3 + 1];
        const float z = pb[j * 3 + 2];
        tile[tid] = make_float4(x, y, z, x * x + y * y + z * z);
        __syncthreads();

        if (t0 == 0) {
            // bootstrap: sub-batches of 16 with flush -> T tightens quickly
            for (int sb = 0; sb < 8; ++sb) {
#pragma unroll
                for (int j2 = 0; j2 < 16; ++j2) {
                    const int jj = sb * 16 + j2;
                    const float4 c = tile[jj];
                    const float dot = qx * c.x + qy * c.y + qz * c.z;
                    const float d2  = (qsq + c.w) - 2.0f * dot;
                    if (d2 < T)
                        buf[tid][cnt++] =
                            ((u64)__float_as_uint(d2) << 32) | (uint32_t)jj;
                }
                FLUSH_BUF();
            }
        } else {
#pragma unroll 4
            for (int jj = 0; jj < 128; ++jj) {
                const float4 c = tile[jj];
                const float dot = qx * c.x + qy * c.y + qz * c.z;
                const float d2  = (qsq + c.w) - 2.0f * dot;
                if (d2 < T) {
                    if (cnt == KNN_CAP) FLUSH_BUF();   // rare inline overflow
                    buf[tid][cnt++] =
                        ((u64)__float_as_uint(d2) << 32) | (uint32_t)(t0 + jj);
                }
            }
            FLUSH_BUF();
        }
        __syncthreads();
    }

    const int base = (b * PP + q) * KK;
#pragma unroll
    for (int s = 0; s < KK; ++s) g_nbr[base + s] = ki[s];
#undef CHAIN_INSERT
#undef FLUSH_BUF
}

// ---------------------------------------------------------------------------
// Weight prep: fp16 fragments (col-major [n,k]) for W1b, W2b, W2a[0:128].
// ---------------------------------------------------------------------------
__global__ void wprep_kernel(const float* __restrict__ W1b,
                             const float* __restrict__ W2b,
                             const float* __restrict__ W2a) {
    const int nt = blockIdx.x, kc = blockIdx.y, L = blockIdx.z;
    const int l  = threadIdx.x;
    const float* W = (L == 0) ? W1b : ((L == 1) ? W2b : W2a);
    const int n  = nt * 8 + (l >> 2);
    const int k0 = kc * 16 + (l & 3) * 2;

    float v[4];
    v[0] = W[(k0 + 0) * NH + n];
    v[1] = W[(k0 + 1) * NH + n];
    v[2] = W[(k0 + 8) * NH + n];
    v[3] = W[(k0 + 9) * NH + n];
    const int idx = (nt * 8 + kc) * 32 + l;
    g_wfh[L][idx] = make_uint2(pack_h2(v[0], v[1]), pack_h2(v[2], v[3]));
}

// ---------------------------------------------------------------------------
// Init pooled max to 0 (relu outputs are >= 0, so 0 is the identity).
// ---------------------------------------------------------------------------
__global__ void gmax_init_kernel() {
    g_gmax[blockIdx.x][threadIdx.x] = 0;
}

// ---------------------------------------------------------------------------
// Edge-conv layer via mma.sync fp16 (fp32 accumulate). CTA = 8 pts = 128 edges.
// GEMM: 4 n-tiles fused per A-fragment. MODE1 additionally computes
// t = h1 @ W2a + b2a in-kernel (mini-MMA) and writes only g_t.
// MODE2 folds global max pool: per-CTA max -> atomicMax into g_gmax
// (int-reinterpret of non-negative floats: exact, order-independent).
// ---------------------------------------------------------------------------
template <int MODE>
__global__ __launch_bounds__(128, 5) void layer_mma(
    const float* __restrict__ pos,
    const float* __restrict__ Wsmall,   // MODE1: W1a[6,128]; MODE2: W2a rows 128..130
    const float* __restrict__ bh,       // MODE1: b1a
    const float* __restrict__ bo,       // MODE1: b1b; MODE2: b2b
    const float* __restrict__ b2a)      // MODE1 only
{
    extern __shared__ char dsm[];
    __shared__ float sM[8][KK][6];
    __shared__ int   sJ[8][KK];

    const int tid = threadIdx.x;
    const int wid = tid >> 5, lid = tid & 31;
    const int p0  = blockIdx.x * 8;
    const int L   = MODE - 1;

    char* actH = (char*)(((uintptr_t)dsm + 1023) & ~(uintptr_t)1023);
    char* h1t  = actH + 32768;          // MODE1: 4KB fp16 h1 tile (16 rows x 128)

    // MODE1: zero h1 tile rows 8-15 (bytes [2048,4096))
    if (MODE == 1)
        *(uint4*)(h1t + 2048 + tid * 16) = make_uint4(0u, 0u, 0u, 0u);

    // ---- neighbor / message prep: thread -> (pt = tid>>4, k = tid&15) ------
    {
        const int pt = tid >> 4, k = tid & 15;
        const int p  = p0 + pt;
        const int b  = p / PP;
        const int jg = b * PP + g_nbr[p * KK + k];
        sJ[pt][k] = jg;
        const float pjx = pos[jg * 3 + 0], pjy = pos[jg * 3 + 1], pjz = pos[jg * 3 + 2];
        const float pix = pos[p * 3 + 0],  piy = pos[p * 3 + 1],  piz = pos[p * 3 + 2];
        if (MODE == 1) {
            sM[pt][k][0] = pjx; sM[pt][k][1] = pjy; sM[pt][k][2] = pjz;
            sM[pt][k][3] = pjx - pix; sM[pt][k][4] = pjy - piy; sM[pt][k][5] = pjz - piz;
        } else {
            sM[pt][k][0] = pjx - pix; sM[pt][k][1] = pjy - piy; sM[pt][k][2] = pjz - piz;
        }
    }
    __syncthreads();

    // ---- Stage A: warp w builds edges 32w..32w+31; lane owns dims 4l..4l+3 -
    {
        const int d0 = lid * 4;
        float4 wsm4[6];
        const int NSM = (MODE == 1) ? 6 : 3;
#pragma unroll
        for (int u = 0; u < 6; ++u)
            wsm4[u] = (u < NSM) ? *(const float4*)&Wsmall[u * NH + d0]
                                : make_float4(0.f, 0.f, 0.f, 0.f);
        float4 bh4 = make_float4(0.f, 0.f, 0.f, 0.f);
        if (MODE == 1) bh4 = *(const float4*)&bh[d0];

        const uint32_t lane_off = (((uint32_t)(lid >> 1)) << 4) + ((lid & 1) << 3);

#pragma unroll 4
        for (int i = 0; i < 32; ++i) {
            const int e  = wid * 32 + i;
            const int pt = e >> 4, k = e & 15;
            float h0, h1, h2, h3;
            if (MODE == 1) {
                h0 = bh4.x; h1 = bh4.y; h2 = bh4.z; h3 = bh4.w;
#pragma unroll
                for (int u = 0; u < 6; ++u) {
                    const float mu = sM[pt][k][u];
                    h0 = fmaf(mu, wsm4[u].x, h0);
                    h1 = fmaf(mu, wsm4[u].y, h1);
                    h2 = fmaf(mu, wsm4[u].z, h2);
                    h3 = fmaf(mu, wsm4[u].w, h3);
                }
            } else {
                const float4 t4 = *(const float4*)&g_t[(size_t)sJ[pt][k] * NH + d0];
                h0 = t4.x; h1 = t4.y; h2 = t4.z; h3 = t4.w;
#pragma unroll
                for (int u = 0; u < 3; ++u) {
                    const float mu = sM[pt][k][u];
                    h0 = fmaf(mu, wsm4[u].x, h0);
                    h1 = fmaf(mu, wsm4[u].y, h1);
                    h2 = fmaf(mu, wsm4[u].z, h2);
                    h3 = fmaf(mu, wsm4[u].w, h3);
                }
            }
            h0 = fmaxf(h0, 0.f); h1 = fmaxf(h1, 0.f);
            h2 = fmaxf(h2, 0.f); h3 = fmaxf(h3, 0.f);

            // row e layout: byte(d) = e*256 + (((d>>3)^(e&7))<<4) + ((d*2)&15)
            const uint32_t off = (uint32_t)e * 256 +
                                 (lane_off ^ (((uint32_t)(e & 7)) << 4));
            *(uint2*)(actH + off) = make_uint2(pack_h2(h0, h1), pack_h2(h2, h3));
        }
    }
    __syncthreads();

    // ---- GEMM: mt-half outer, 4 n-tiles fused per A-fragment ---------------
    const uint32_t aHs = smem_u32(actH);
    const int rowl  = (lid & 15);
    const int kxofs = (lid >> 4) & 1;

    float gmx[4][2];                      // MODE2: running max per (j, val01)
#pragma unroll
    for (int j = 0; j < 4; ++j) { gmx[j][0] = 0.f; gmx[j][1] = 0.f; }

#pragma unroll
    for (int mh = 0; mh < 2; ++mh) {
        float acc[4][4][4];
#pragma unroll
        for (int mt = 0; mt < 4; ++mt)
#pragma unroll
            for (int j = 0; j < 4; ++j)
#pragma unroll
                for (int c = 0; c < 4; ++c) acc[mt][j][c] = 0.f;

#pragma unroll
        for (int kc = 0; kc < 8; ++kc) {
            uint2 bf[4];
#pragma unroll
            for (int j = 0; j < 4; ++j)
                bf[j] = g_wfh[L][((wid * 4 + j) * 8 + kc) * 32 + lid];
            const int kx = kc * 2 + kxofs;

#pragma unroll
            for (int mt = 0; mt < 4; ++mt) {
                const int r = (mh * 4 + mt) * 16 + rowl;
                const uint32_t off = ((uint32_t)r << 8) +
                                     ((uint32_t)(kx ^ (r & 7)) << 4);
                uint32_t ah[4];
                ldsm_x4(ah, aHs + off);
                mma_f16(acc[mt][0], ah, bf[0]);
                mma_f16(acc[mt][1], ah, bf[1]);
                mma_f16(acc[mt][2], ah, bf[2]);
                mma_f16(acc[mt][3], ah, bf[3]);
            }
        }

        // epilogue: max over 16 edge rows per point, bias, relu
#pragma unroll
        for (int mt = 0; mt < 4; ++mt) {
            const int prow = mh * 4 + mt;            // point index in CTA
#pragma unroll
            for (int j = 0; j < 4; ++j) {
                float c0 = fmaxf(acc[mt][j][0], acc[mt][j][2]);
                float c1 = fmaxf(acc[mt][j][1], acc[mt][j][3]);
#pragma unroll
                for (int s = 4; s <= 16; s <<= 1) {
                    c0 = fmaxf(c0, __shfl_xor_sync(0xffffffffu, c0, s));
                    c1 = fmaxf(c1, __shfl_xor_sync(0xffffffffu, c1, s));
                }
                if (MODE == 1) {
                    if (lid < 4) {
                        const int nt = wid * 4 + j;
                        const int n0 = nt * 8 + 2 * lid;
                        const float2 bv = *(const float2*)&bo[n0];
                        const float o0 = fmaxf(c0 + bv.x, 0.f);
                        const float o1 = fmaxf(c1 + bv.y, 0.f);
                        // h1 -> fp16 smem tile (row = prow, cols n0,n0+1)
                        const uint32_t hoff = (uint32_t)prow * 256 +
                            ((uint32_t)(nt ^ prow) << 4) + (uint32_t)(4 * lid);
                        *(uint32_t*)(h1t + hoff) = pack_h2(o0, o1);
                    }
                } else {
                    // fold point-max into CTA-max (valid on all lanes)
                    const int n0 = (wid * 4 + j) * 8 + 2 * (lid & 3);
                    const float2 bv = *(const float2*)&bo[n0];
                    gmx[j][0] = fmaxf(gmx[j][0], fmaxf(c0 + bv.x, 0.f));
                    gmx[j][1] = fmaxf(gmx[j][1], fmaxf(c1 + bv.y, 0.f));
                }
            }
        }
    }

    if (MODE == 2) {
        // one atomic per (dim) from lid<4; values >= 0 so int-max == float-max
        const int b = p0 / PP;
        if (lid < 4) {
#pragma unroll
            for (int j = 0; j < 4; ++j) {
                const int n0 = (wid * 4 + j) * 8 + 2 * lid;
                atomicMax(&g_gmax[b][n0],     __float_as_int(gmx[j][0]));
                atomicMax(&g_gmax[b][n0 + 1], __float_as_int(gmx[j][1]));
            }
        }
    }

    // ---- MODE1 mini-GEMM: t[8,128] = h1[8,128] @ W2a[0:128] + b2a ----------
    if (MODE == 1) {
        __syncthreads();
        const uint32_t h1s = smem_u32(h1t);
        float acc2[4][4];
#pragma unroll
        for (int j = 0; j < 4; ++j)
#pragma unroll
            for (int c = 0; c < 4; ++c) acc2[j][c] = 0.f;

#pragma unroll
        for (int kc = 0; kc < 8; ++kc) {
            const int kx = kc * 2 + kxofs;
            const uint32_t off = ((uint32_t)rowl << 8) +
                                 ((uint32_t)(kx ^ (rowl & 7)) << 4);
            uint32_t ah[4];
            ldsm_x4(ah, h1s + off);
#pragma unroll
            for (int j = 0; j < 4; ++j) {
                const uint2 bf = g_wfh[2][((wid * 4 + j) * 8 + kc) * 32 + lid];
                mma_f16(acc2[j], ah, bf);
            }
        }

        // store rows 0-7 (d0,d1 -> row = lid>>2, cols 2*(lid&3)+{0,1})
        const int row = lid >> 2;
#pragma unroll
        for (int j = 0; j < 4; ++j) {
            const int n0 = (wid * 4 + j) * 8 + 2 * (lid & 3);
            const float2 bv = *(const float2*)&b2a[n0];
            *(float2*)&g_t[(size_t)(p0 + row) * NH + n0] =
                make_float2(acc2[j][0] + bv.x, acc2[j][1] + bv.y);
        }
    }
}

// ---------------------------------------------------------------------------
// Classifier: out[b] = g_gmax[b] @ Wc + bc
// ---------------------------------------------------------------------------
__global__ void cls_kernel(const float* __restrict__ Wc,
                           const float* __restrict__ bc,
                           float* __restrict__ out) {
    const int b   = blockIdx.x;
    const int tid = threadIdx.x;

    __shared__ float sg[NH];
    sg[tid] = __int_as_float(g_gmax[b][tid]);
    __syncthreads();

    if (tid < 10) {
        float a = bc[tid];
#pragma unroll 8
        for (int d = 0; d < NH; ++d) a = fmaf(sg[d], Wc[d * 10 + tid], a);
        out[b * 10 + tid] = a;
    }
}

// ---------------------------------------------------------------------------
extern "C" void kernel_launch(void* const* d_in, const int* in_sizes, int n_in,
                              void* d_out, int out_size) {
    const float* pos = (const float*)d_in[0];
    const float* W1a = (const float*)d_in[2];
    const float* b1a = (const float*)d_in[3];
    const float* W1b = (const float*)d_in[4];
    const float* b1b = (const float*)d_in[5];
    const float* W2a = (const float*)d_in[6];
    const float* b2a = (const float*)d_in[7];
    const float* W2b = (const float*)d_in[8];
    const float* b2b = (const float*)d_in[9];
    const float* Wc  = (const float*)d_in[10];
    const float* bc  = (const float*)d_in[11];
    float* out = (float*)d_out;

    const int DSM1 = 32768 + 4096 + 1024;  // act tile + h1 tile + pad
    const int DSM2 = 32768 + 1024;         // act tile + pad
    cudaFuncSetAttribute(layer_mma<1>, cudaFuncAttributeMaxDynamicSharedMemorySize, DSM1);
    cudaFuncSetAttribute(layer_mma<2>, cudaFuncAttributeMaxDynamicSharedMemorySize, DSM2);

    wprep_kernel<<<dim3(16, 8, 3), 32>>>(W1b, W2b, W2a);
    gmax_init_kernel<<<BB, NH>>>();
    knn_kernel<<<dim3(PP / 128, BB), 128>>>(pos);
    layer_mma<1><<<BB * PP / 8, 128, DSM1>>>(pos, W1a, b1a, b1b, b2a);
    layer_mma<2><<<BB * PP / 8, 128, DSM2>>>(pos, W2a + 128 * NH, nullptr, b2b, nullptr);
    cls_kernel<<<BB, 128>>>(Wc, bc, out);
}